// round 14
// baseline (speedup 1.0000x reference)
#include <cuda_runtime.h>
#include <cuda_bf16.h>
#include <math_constants.h>

// Shapes (fixed for this problem)
#define B  32
#define S  4096
#define H  1024
#define D  2048   // 2*H

#define HS 16           // h-splits for vpart
#define HC (H / HS)     // 64 h per split
#define BG 8            // batches per vpart CTA

#define CPB 14          // CTAs per batch in k_energy (448 total)
#define QPB (S / 4)     // 1024 warp-quanta (4 rows) per batch

// Scratch (device globals; no allocation allowed)
__device__ float g_vpart[HS][B * D];  // h-split partials of v = W^T hidden
__device__ float g_v[B * D];
__device__ float g_energy[B * S];
__device__ unsigned int g_tick[B * 32];  // per-batch tickets, 128B apart

// ---------------------------------------------------------------------------
// Kernel 0: reset per-batch tickets (deterministic, graph-capturable)
// ---------------------------------------------------------------------------
__global__ void k_reset() { g_tick[threadIdx.x * 32] = 0u; }

// ---------------------------------------------------------------------------
// Kernel 1: v_part[hs][b][d] = sum_{h in chunk hs} hidden[b][h] * W[h][d]
// grid (D/128, B/8, HS) = 1024 CTAs, block 128. hsm transposed: the 8 batch
// values per iter come from 2 LDS.128.
// ---------------------------------------------------------------------------
__global__ __launch_bounds__(128) void k_vpart(const float* __restrict__ hidden,
                                               const float* __restrict__ W) {
    const int tid = threadIdx.x;
    const int d   = blockIdx.x * 128 + tid;
    const int bg  = blockIdx.y;           // batch group of 8
    const int hs  = blockIdx.z;           // h chunk of HC

    __shared__ float4 hsm4[HC][2];        // [hl][jj] : 8 batches as 2 float4
    for (int idx = tid; idx < BG * HC; idx += 128) {
        int j = idx & 7, hl = idx >> 3;
        reinterpret_cast<float*>(hsm4)[hl * 8 + j] =
            hidden[(bg * BG + j) * H + hs * HC + hl];
    }
    __syncthreads();

    float acc[8];
#pragma unroll
    for (int j = 0; j < 8; ++j) acc[j] = 0.f;

    const float* Wp = W + (size_t)(hs * HC) * D + d;
#pragma unroll 16
    for (int hl = 0; hl < HC; ++hl) {
        float w = Wp[(size_t)hl * D];
        float4 h0 = hsm4[hl][0];
        float4 h1 = hsm4[hl][1];
        acc[0] += h0.x * w;  acc[1] += h0.y * w;
        acc[2] += h0.z * w;  acc[3] += h0.w * w;
        acc[4] += h1.x * w;  acc[5] += h1.y * w;
        acc[6] += h1.z * w;  acc[7] += h1.w * w;
    }

#pragma unroll
    for (int j = 0; j < 8; ++j)
        g_vpart[hs][(bg * BG + j) * D + d] = acc[j];
}

// ---------------------------------------------------------------------------
// Kernel 1b: v = sum of HS partials, float4-vectorized (deterministic)
// ---------------------------------------------------------------------------
__global__ void k_vreduce() {
    int idx = blockIdx.x * blockDim.x + threadIdx.x;   // B*D/4 threads
    if (idx < B * D / 4) {
        float4 s = make_float4(0.f, 0.f, 0.f, 0.f);
#pragma unroll
        for (int p = 0; p < HS; ++p) {
            float4 a = reinterpret_cast<const float4*>(g_vpart[p])[idx];
            s.x += a.x; s.y += a.y; s.z += a.z; s.w += a.w;
        }
        reinterpret_cast<float4*>(g_v)[idx] = s;
    }
}

// ---------------------------------------------------------------------------
// Kernel 2: energies[b][s] = dot(enc[b][s][:], v[b][:])
// BATCH-PINNED persistent CTAs + per-WARP atomic tickets:
//   - 448 CTAs (14 per batch); vsm staged ONCE, read-only after -> zero
//     barriers in the steady loop (the R5 persistent failure was the
//     per-tile barrier drain, not persistence).
//   - warps grab 4-row quanta from their batch's ticket (lane0 atomicAdd
//     + shfl, next ticket prefetched to hide ATOMG latency) -> no tail
//     wave: recovers the ~60%-full 5th wave (~8-10% of runtime).
// ---------------------------------------------------------------------------
__global__ __launch_bounds__(512, 3) void k_energy(const float* __restrict__ enc) {
    const int tid  = threadIdx.x;
    const int lane = tid & 31;
    const int b    = blockIdx.x / CPB;       // pinned batch

    __shared__ float4 vsm[D / 4];   // 8KB

    vsm[tid] = reinterpret_cast<const float4*>(g_v + b * D)[tid];
    __syncthreads();               // only barrier; vsm read-only afterwards

    unsigned int* tick = &g_tick[b * 32];
    const float* encb = enc + (size_t)b * S * D;

    // first ticket
    unsigned int t = 0u;
    if (lane == 0) t = atomicAdd(tick, 1u);
    t = __shfl_sync(0xFFFFFFFFu, t, 0);

    while (t < QPB) {
        // prefetch next ticket (overlaps with this quantum's work)
        unsigned int tn = 0u;
        if (lane == 0) tn = atomicAdd(tick, 1u);
        tn = __shfl_sync(0xFFFFFFFFu, tn, 0);

        const int s0 = (int)t * 4;
#pragma unroll
        for (int r = 0; r < 4; ++r) {
            const int s = s0 + r;
            const float4* e4 = reinterpret_cast<const float4*>(
                encb + (size_t)s * D);
            float acc = 0.f;
#pragma unroll
            for (int i = 0; i < 16; ++i) {
                float4 e = __ldcs(&e4[i * 32 + lane]);
                float4 v = vsm[i * 32 + lane];
                acc += e.x * v.x + e.y * v.y + e.z * v.z + e.w * v.w;
            }
#pragma unroll
            for (int off = 16; off > 0; off >>= 1)
                acc += __shfl_xor_sync(0xFFFFFFFFu, acc, off);
            if (lane == 0) g_energy[b * S + s] = acc;
        }
        t = tn;
    }
}

// ---------------------------------------------------------------------------
// Kernel 3: per-batch ONLINE softmax over S (single (m,s) reduction round).
// One block per batch, 512 threads, 8 elems/thread. Bias dropped
// (constant per row, cancels in softmax).
// ---------------------------------------------------------------------------
__global__ __launch_bounds__(512) void k_softmax(float* __restrict__ out) {
    const int b   = blockIdx.x;
    const int tid = threadIdx.x;
    __shared__ float red_m[16], red_s[16];

    float e[8];
    float m = -CUDART_INF_F;
#pragma unroll
    for (int i = 0; i < 8; ++i) {
        e[i] = g_energy[b * S + tid + i * 512];
        m = fmaxf(m, e[i]);
    }
    float s = 0.f;
#pragma unroll
    for (int i = 0; i < 8; ++i) s += __expf(e[i] - m);

#pragma unroll
    for (int off = 16; off > 0; off >>= 1) {
        float mo = __shfl_xor_sync(0xFFFFFFFFu, m, off);
        float so = __shfl_xor_sync(0xFFFFFFFFu, s, off);
        float M  = fmaxf(m, mo);
        s = s * __expf(m - M) + so * __expf(mo - M);
        m = M;
    }
    if ((tid & 31) == 0) { red_m[tid >> 5] = m; red_s[tid >> 5] = s; }
    __syncthreads();
    if (tid < 32) {
        float mm = (tid < 16) ? red_m[tid] : -CUDART_INF_F;
        float ss = (tid < 16) ? red_s[tid] : 0.f;
#pragma unroll
        for (int off = 8; off > 0; off >>= 1) {
            float mo = __shfl_xor_sync(0xFFFFFFFFu, mm, off);
            float so = __shfl_xor_sync(0xFFFFFFFFu, ss, off);
            float M  = fmaxf(mm, mo);
            ss = ss * __expf(mm - M) + so * __expf(mo - M);
            mm = M;
        }
        if (tid == 0) { red_m[0] = mm; red_s[0] = ss; }
    }
    __syncthreads();
    const float M   = red_m[0];
    const float inv = 1.0f / red_s[0];

#pragma unroll
    for (int i = 0; i < 8; ++i)
        out[b * S + tid + i * 512] = __expf(e[i] - M) * inv;
}

// ---------------------------------------------------------------------------
extern "C" void kernel_launch(void* const* d_in, const int* in_sizes, int n_in,
                              void* d_out, int out_size) {
    const float* hidden = (const float*)d_in[0];   // [B,H]
    const float* enc    = (const float*)d_in[1];   // [B,S,2H]
    const float* W      = (const float*)d_in[2];   // [H,2H]
    // d_in[3] = bias: constant per row -> cancels in softmax, unused.
    float* out = (float*)d_out;                    // [B,1,S]

    k_reset<<<1, B>>>();
    k_vpart<<<dim3(D / 128, B / BG, HS), 128>>>(hidden, W);
    k_vreduce<<<(B * D / 4 + 255) / 256, 256>>>();
    k_energy<<<B * CPB, 512>>>(enc);
    k_softmax<<<B, 512>>>(out);
}

// round 15
// speedup vs baseline: 1.9608x; 1.9608x over previous
#include <cuda_runtime.h>
#include <cuda_bf16.h>
#include <math_constants.h>

// Shapes (fixed for this problem)
#define B  32
#define S  4096
#define H  1024
#define D  2048   // 2*H

#define HS 16           // h-splits for vpart
#define HC (H / HS)     // 64 h per split
#define BG 8            // batches per vpart CTA

// Scratch (device globals; no allocation allowed)
__device__ float g_vpart[HS][B * D];  // h-split partials of v = W^T hidden
__device__ float g_v[B * D];
__device__ float g_energy[B * S];

// ---------------------------------------------------------------------------
// Kernel 1: v_part[hs][b][d] = sum_{h in chunk hs} hidden[b][h] * W[h][d]
// grid (D/128, B/8, HS) = 1024 CTAs, block 128. hsm transposed: the 8 batch
// values per iter come from 2 LDS.128.
// ---------------------------------------------------------------------------
__global__ __launch_bounds__(128) void k_vpart(const float* __restrict__ hidden,
                                               const float* __restrict__ W) {
    const int tid = threadIdx.x;
    const int d   = blockIdx.x * 128 + tid;
    const int bg  = blockIdx.y;           // batch group of 8
    const int hs  = blockIdx.z;           // h chunk of HC

    __shared__ float4 hsm4[HC][2];        // [hl][jj] : 8 batches as 2 float4
    for (int idx = tid; idx < BG * HC; idx += 128) {
        int j = idx & 7, hl = idx >> 3;
        reinterpret_cast<float*>(hsm4)[hl * 8 + j] =
            hidden[(bg * BG + j) * H + hs * HC + hl];
    }
    __syncthreads();

    float acc[8];
#pragma unroll
    for (int j = 0; j < 8; ++j) acc[j] = 0.f;

    const float* Wp = W + (size_t)(hs * HC) * D + d;
#pragma unroll 16
    for (int hl = 0; hl < HC; ++hl) {
        float w = Wp[(size_t)hl * D];
        float4 h0 = hsm4[hl][0];
        float4 h1 = hsm4[hl][1];
        acc[0] += h0.x * w;  acc[1] += h0.y * w;
        acc[2] += h0.z * w;  acc[3] += h0.w * w;
        acc[4] += h1.x * w;  acc[5] += h1.y * w;
        acc[6] += h1.z * w;  acc[7] += h1.w * w;
    }

#pragma unroll
    for (int j = 0; j < 8; ++j)
        g_vpart[hs][(bg * BG + j) * D + d] = acc[j];
}

// ---------------------------------------------------------------------------
// Kernel 1b: v = sum of HS partials, float4-vectorized (deterministic)
// ---------------------------------------------------------------------------
__global__ void k_vreduce() {
    int idx = blockIdx.x * blockDim.x + threadIdx.x;   // B*D/4 threads
    if (idx < B * D / 4) {
        float4 s = make_float4(0.f, 0.f, 0.f, 0.f);
#pragma unroll
        for (int p = 0; p < HS; ++p) {
            float4 a = reinterpret_cast<const float4*>(g_vpart[p])[idx];
            s.x += a.x; s.y += a.y; s.z += a.z; s.w += a.w;
        }
        reinterpret_cast<float4*>(g_v)[idx] = s;
    }
}

// ---------------------------------------------------------------------------
// Kernel 2: energies[b][s] = dot(enc[b][s][:], v[b][:])
// ROUND-1 REGISTER-RESIDENT FORM (A/B test vs smem version): each warp holds
// v[b] in 16 float4 regs, 4 rows per warp, no launch_bounds (compiler picks
// regs; ~1-2 CTA/SM). Zero-LDS inner loop issues the full 16-load burst
// with no smem dependency. Multi-wave one-tile-per-CTA (persistence is
// 2x slower — measured 3x). grid (S/64, B), block 512.
// ---------------------------------------------------------------------------
__global__ void k_energy(const float* __restrict__ enc) {
    const int b    = blockIdx.y;
    const int warp = threadIdx.x >> 5;
    const int lane = threadIdx.x & 31;
    const int s0   = blockIdx.x * 64 + warp * 4;

    const float4* v4 = reinterpret_cast<const float4*>(g_v + b * D);
    float4 vv[16];
#pragma unroll
    for (int i = 0; i < 16; ++i) vv[i] = v4[i * 32 + lane];

#pragma unroll
    for (int r = 0; r < 4; ++r) {
        const int s = s0 + r;
        const float4* e4 = reinterpret_cast<const float4*>(
            enc + ((size_t)b * S + s) * D);
        float acc = 0.f;
#pragma unroll
        for (int i = 0; i < 16; ++i) {
            float4 e = __ldcs(&e4[i * 32 + lane]);
            acc += e.x * vv[i].x + e.y * vv[i].y
                 + e.z * vv[i].z + e.w * vv[i].w;
        }
#pragma unroll
        for (int off = 16; off > 0; off >>= 1)
            acc += __shfl_xor_sync(0xFFFFFFFFu, acc, off);
        if (lane == 0) g_energy[b * S + s] = acc;
    }
}

// ---------------------------------------------------------------------------
// Kernel 3: per-batch ONLINE softmax over S (single (m,s) reduction round).
// One block per batch, 512 threads, 8 elems/thread. Bias dropped
// (constant per row, cancels in softmax).
// ---------------------------------------------------------------------------
__global__ __launch_bounds__(512) void k_softmax(float* __restrict__ out) {
    const int b   = blockIdx.x;
    const int tid = threadIdx.x;
    __shared__ float red_m[16], red_s[16];

    float e[8];
    float m = -CUDART_INF_F;
#pragma unroll
    for (int i = 0; i < 8; ++i) {
        e[i] = g_energy[b * S + tid + i * 512];
        m = fmaxf(m, e[i]);
    }
    float s = 0.f;
#pragma unroll
    for (int i = 0; i < 8; ++i) s += __expf(e[i] - m);

#pragma unroll
    for (int off = 16; off > 0; off >>= 1) {
        float mo = __shfl_xor_sync(0xFFFFFFFFu, m, off);
        float so = __shfl_xor_sync(0xFFFFFFFFu, s, off);
        float M  = fmaxf(m, mo);
        s = s * __expf(m - M) + so * __expf(mo - M);
        m = M;
    }
    if ((tid & 31) == 0) { red_m[tid >> 5] = m; red_s[tid >> 5] = s; }
    __syncthreads();
    if (tid < 32) {
        float mm = (tid < 16) ? red_m[tid] : -CUDART_INF_F;
        float ss = (tid < 16) ? red_s[tid] : 0.f;
#pragma unroll
        for (int off = 8; off > 0; off >>= 1) {
            float mo = __shfl_xor_sync(0xFFFFFFFFu, mm, off);
            float so = __shfl_xor_sync(0xFFFFFFFFu, ss, off);
            float M  = fmaxf(mm, mo);
            ss = ss * __expf(mm - M) + so * __expf(mo - M);
            mm = M;
        }
        if (tid == 0) { red_m[0] = mm; red_s[0] = ss; }
    }
    __syncthreads();
    const float M   = red_m[0];
    const float inv = 1.0f / red_s[0];

#pragma unroll
    for (int i = 0; i < 8; ++i)
        out[b * S + tid + i * 512] = __expf(e[i] - M) * inv;
}

// ---------------------------------------------------------------------------
extern "C" void kernel_launch(void* const* d_in, const int* in_sizes, int n_in,
                              void* d_out, int out_size) {
    const float* hidden = (const float*)d_in[0];   // [B,H]
    const float* enc    = (const float*)d_in[1];   // [B,S,2H]
    const float* W      = (const float*)d_in[2];   // [H,2H]
    // d_in[3] = bias: constant per row -> cancels in softmax, unused.
    float* out = (float*)d_out;                    // [B,1,S]

    k_vpart<<<dim3(D / 128, B / BG, HS), 128>>>(hidden, W);
    k_vreduce<<<(B * D / 4 + 255) / 256, 256>>>();
    k_energy<<<dim3(S / 64, B), 512>>>(enc);
    k_softmax<<<B, 512>>>(out);
}

// round 16
// speedup vs baseline: 2.1668x; 1.1050x over previous
#include <cuda_runtime.h>
#include <cuda_bf16.h>
#include <math_constants.h>

// Shapes (fixed for this problem)
#define B  32
#define S  4096
#define H  1024
#define D  2048   // 2*H

#define HS 16           // h-splits for vpart
#define HC (H / HS)     // 64 h per split
#define BG 8            // batches per vpart CTA

#define TOTROWS (B * S)          // 131072 flattened rows
#define NCTA_E  1776             // exactly 4 waves of 148 SMs * 3 CTAs
#define NWARP_E (NCTA_E * 16)    // 28416 warps

// Scratch (device globals; no allocation allowed)
__device__ float g_vpart[HS][B * D];  // h-split partials of v = W^T hidden
__device__ float g_v[B * D];
__device__ float g_energy[B * S];

// ---------------------------------------------------------------------------
// Kernel 1: v_part[hs][b][d] = sum_{h in chunk hs} hidden[b][h] * W[h][d]
// grid (D/128, B/8, HS) = 1024 CTAs, block 128. hsm transposed: the 8 batch
// values per iter come from 2 LDS.128.
// ---------------------------------------------------------------------------
__global__ __launch_bounds__(128) void k_vpart(const float* __restrict__ hidden,
                                               const float* __restrict__ W) {
    const int tid = threadIdx.x;
    const int d   = blockIdx.x * 128 + tid;
    const int bg  = blockIdx.y;           // batch group of 8
    const int hs  = blockIdx.z;           // h chunk of HC

    __shared__ float4 hsm4[HC][2];        // [hl][jj] : 8 batches as 2 float4
    for (int idx = tid; idx < BG * HC; idx += 128) {
        int j = idx & 7, hl = idx >> 3;
        reinterpret_cast<float*>(hsm4)[hl * 8 + j] =
            hidden[(bg * BG + j) * H + hs * HC + hl];
    }
    __syncthreads();

    float acc[8];
#pragma unroll
    for (int j = 0; j < 8; ++j) acc[j] = 0.f;

    const float* Wp = W + (size_t)(hs * HC) * D + d;
#pragma unroll 16
    for (int hl = 0; hl < HC; ++hl) {
        float w = Wp[(size_t)hl * D];
        float4 h0 = hsm4[hl][0];
        float4 h1 = hsm4[hl][1];
        acc[0] += h0.x * w;  acc[1] += h0.y * w;
        acc[2] += h0.z * w;  acc[3] += h0.w * w;
        acc[4] += h1.x * w;  acc[5] += h1.y * w;
        acc[6] += h1.z * w;  acc[7] += h1.w * w;
    }

#pragma unroll
    for (int j = 0; j < 8; ++j)
        g_vpart[hs][(bg * BG + j) * D + d] = acc[j];
}

// ---------------------------------------------------------------------------
// Kernel 1b: v = sum of HS partials, float4-vectorized (deterministic)
// ---------------------------------------------------------------------------
__global__ void k_vreduce() {
    int idx = blockIdx.x * blockDim.x + threadIdx.x;   // B*D/4 threads
    if (idx < B * D / 4) {
        float4 s = make_float4(0.f, 0.f, 0.f, 0.f);
#pragma unroll
        for (int p = 0; p < HS; ++p) {
            float4 a = reinterpret_cast<const float4*>(g_vpart[p])[idx];
            s.x += a.x; s.y += a.y; s.z += a.z; s.w += a.w;
        }
        reinterpret_cast<float4*>(g_v)[idx] = s;
    }
}

// ---------------------------------------------------------------------------
// Kernel 2: energies[row] = dot(enc[row][:], v[row>>12][:])
// Flat warp-granular split, NO smem:
//   - v read via __ldg; contiguous per-warp row ranges keep a warp's rows
//     in (almost always) one batch -> v L1-hits after the first row.
//   - no vsm staging, no __syncthreads at all.
//   - 1776 CTAs = EXACTLY 4 waves (148 SMs x 3 CTAs) -> no ragged drain
//     wave (2048-CTA version had a 61%-full 5th wave).
// Inner row loop unchanged (proven best). block 512, 3 CTAs/SM.
// ---------------------------------------------------------------------------
__global__ __launch_bounds__(512, 3) void k_energy(const float* __restrict__ enc) {
    const int  lane = threadIdx.x & 31;
    const long gw   = (long)blockIdx.x * 16 + (threadIdx.x >> 5);

    const int r0 = (int)((gw * (long)TOTROWS) / NWARP_E);
    const int r1 = (int)(((gw + 1) * (long)TOTROWS) / NWARP_E);

    for (int r = r0; r < r1; ++r) {
        const float4* v4 = reinterpret_cast<const float4*>(
            g_v + (size_t)(r >> 12) * D);
        const float4* e4 = reinterpret_cast<const float4*>(
            enc + (size_t)r * D);
        float acc = 0.f;
#pragma unroll
        for (int i = 0; i < 16; ++i) {
            float4 e = __ldcs(&e4[i * 32 + lane]);
            float4 v = __ldg(&v4[i * 32 + lane]);
            acc += e.x * v.x + e.y * v.y + e.z * v.z + e.w * v.w;
        }
#pragma unroll
        for (int off = 16; off > 0; off >>= 1)
            acc += __shfl_xor_sync(0xFFFFFFFFu, acc, off);
        if (lane == 0) g_energy[r] = acc;
    }
}

// ---------------------------------------------------------------------------
// Kernel 3: per-batch ONLINE softmax over S (single (m,s) reduction round).
// One block per batch, 512 threads, 8 elems/thread. Bias dropped
// (constant per row, cancels in softmax).
// ---------------------------------------------------------------------------
__global__ __launch_bounds__(512) void k_softmax(float* __restrict__ out) {
    const int b   = blockIdx.x;
    const int tid = threadIdx.x;
    __shared__ float red_m[16], red_s[16];

    float e[8];
    float m = -CUDART_INF_F;
#pragma unroll
    for (int i = 0; i < 8; ++i) {
        e[i] = g_energy[b * S + tid + i * 512];
        m = fmaxf(m, e[i]);
    }
    float s = 0.f;
#pragma unroll
    for (int i = 0; i < 8; ++i) s += __expf(e[i] - m);

#pragma unroll
    for (int off = 16; off > 0; off >>= 1) {
        float mo = __shfl_xor_sync(0xFFFFFFFFu, m, off);
        float so = __shfl_xor_sync(0xFFFFFFFFu, s, off);
        float M  = fmaxf(m, mo);
        s = s * __expf(m - M) + so * __expf(mo - M);
        m = M;
    }
    if ((tid & 31) == 0) { red_m[tid >> 5] = m; red_s[tid >> 5] = s; }
    __syncthreads();
    if (tid < 32) {
        float mm = (tid < 16) ? red_m[tid] : -CUDART_INF_F;
        float ss = (tid < 16) ? red_s[tid] : 0.f;
#pragma unroll
        for (int off = 8; off > 0; off >>= 1) {
            float mo = __shfl_xor_sync(0xFFFFFFFFu, mm, off);
            float so = __shfl_xor_sync(0xFFFFFFFFu, ss, off);
            float M  = fmaxf(mm, mo);
            ss = ss * __expf(mm - M) + so * __expf(mo - M);
            mm = M;
        }
        if (tid == 0) { red_m[0] = mm; red_s[0] = ss; }
    }
    __syncthreads();
    const float M   = red_m[0];
    const float inv = 1.0f / red_s[0];

#pragma unroll
    for (int i = 0; i < 8; ++i)
        out[b * S + tid + i * 512] = __expf(e[i] - M) * inv;
}

// ---------------------------------------------------------------------------
extern "C" void kernel_launch(void* const* d_in, const int* in_sizes, int n_in,
                              void* d_out, int out_size) {
    const float* hidden = (const float*)d_in[0];   // [B,H]
    const float* enc    = (const float*)d_in[1];   // [B,S,2H]
    const float* W      = (const float*)d_in[2];   // [H,2H]
    // d_in[3] = bias: constant per row -> cancels in softmax, unused.
    float* out = (float*)d_out;                    // [B,1,S]

    k_vpart<<<dim3(D / 128, B / BG, HS), 128>>>(hidden, W);
    k_vreduce<<<(B * D / 4 + 255) / 256, 256>>>();
    k_energy<<<NCTA_E, 512>>>(enc);
    k_softmax<<<B, 512>>>(out);
}